// round 3
// baseline (speedup 1.0000x reference)
#include <cuda_runtime.h>

// TVConv: per-pixel spatially-varying 3x3 depthwise conv.
// x:           (B=8, C=96, H=128, W=128) f32
// weight_maps: (1, C=96, 3, 3, H=128, W=128) f32
// out:         (B=8, C=96, H=128, W=128) f32
//
// CTA = (channel c, 8-row strip), 512 threads, 2 rows/thread -> only 18
// weight registers/thread, reg budget ~40 -> 3 CTAs/SM = 48 warps resident
// (vs 32 before). Weights load once per CTA, reused across all 8 batches.
// x tile (10x128 interior) staged via 16B cp.async double buffer so batch
// b+1's DRAM latency overlaps batch b's compute. Halo columns permanently
// zero; out-of-range halo rows zero-filled via cp.async src-size=0.

#define BB 8
#define CC 96
#define HH 128
#define WW 128
#define TH 8          // output rows per block
#define SPITCH 136    // floats per shared row (4 pad + halo + 128 + halo + pad)
#define TROWS (TH + 2)

__device__ __forceinline__ void cp_async16(void* smem_dst, const void* gsrc, int src_bytes) {
    unsigned saddr = (unsigned)__cvta_generic_to_shared(smem_dst);
    asm volatile("cp.async.cg.shared.global [%0], [%1], 16, %2;\n"
                 :: "r"(saddr), "l"(gsrc), "r"(src_bytes));
}
__device__ __forceinline__ void cp_async_commit() {
    asm volatile("cp.async.commit_group;\n" ::: "memory");
}
template <int N>
__device__ __forceinline__ void cp_async_wait() {
    asm volatile("cp.async.wait_group %0;\n" :: "n"(N) : "memory");
}

__global__ __launch_bounds__(512, 3)
void tvconv_kernel(const float* __restrict__ x,
                   const float* __restrict__ wm,
                   float* __restrict__ out) {
    const int c   = blockIdx.y;
    const int h0  = blockIdx.x * TH;
    const int tid = threadIdx.x;
    const int tw  = tid & (WW - 1);   // 0..127 -> output w
    const int ty  = tid >> 7;         // 0..3

    __shared__ __align__(16) float sx[2][TROWS * SPITCH];

    const int plane = HH * WW;        // 16384
    const float* wmc = wm + c * 9 * plane;

    // ---- halo columns are permanently zero (x zero-pad), both buffers ----
    if (tid < 2 * TROWS * 2) {
        int e   = tid;
        int buf = e & 1;
        int r   = (e >> 1) % TROWS;
        int sid = (e >> 1) / TROWS;   // 0 -> left col, 1 -> right col
        sx[buf][r * SPITCH + (sid == 0 ? 3 : 132)] = 0.0f;
    }

    // ---- load 2x9 weights into registers (coalesced per tap) ----
    float wreg[2][9];
    #pragma unroll
    for (int r = 0; r < 2; r++) {
        const int h = h0 + ty + 4 * r;
        const int base = h * WW + tw;
        #pragma unroll
        for (int t = 0; t < 9; t++) {
            wreg[r][t] = __ldg(&wmc[t * plane + base]);
        }
    }

    const int cplane = c * plane;

    // staging: 10 rows x 32 float4 = 320 tasks, one per thread (tid < 320)
    const int srow = tid >> 5;        // 0..15 (valid < 10)
    const int sk   = tid & 31;        // float4 index within row

    auto stage = [&](int buf, int b) {
        if (tid < TROWS * 32) {
            const float* xb = x + (b * CC) * plane + cplane;
            int gh = h0 - 1 + srow;
            int ok = (gh >= 0 && gh < HH);
            int ghc = ok ? gh : 0;
            cp_async16(&sx[buf][srow * SPITCH + 4 + 4 * sk],
                       xb + ghc * WW + 4 * sk, ok ? 16 : 0);
        }
        cp_async_commit();
    };

    // preload batch 0
    stage(0, 0);

    for (int b = 0; b < BB; b++) {
        const int p = b & 1;
        if (b + 1 < BB) {
            stage(p ^ 1, b + 1);
            cp_async_wait<1>();       // buf p complete; b+1 still in flight
        } else {
            cp_async_wait<0>();
        }
        __syncthreads();

        float* ob = out + (b * CC) * plane + cplane;
        #pragma unroll
        for (int r = 0; r < 2; r++) {
            const int lr = ty + 4 * r;            // local output row 0..7
            float acc = 0.0f;
            #pragma unroll
            for (int kh = 0; kh < 3; kh++) {
                const float* sr = &sx[p][(lr + kh) * SPITCH + tw + 3];
                acc = fmaf(wreg[r][kh * 3 + 0], sr[0], acc);
                acc = fmaf(wreg[r][kh * 3 + 1], sr[1], acc);
                acc = fmaf(wreg[r][kh * 3 + 2], sr[2], acc);
            }
            ob[(h0 + lr) * WW + tw] = acc;
        }
        __syncthreads();   // buf p refilled at iter b+1's stage
    }
}

extern "C" void kernel_launch(void* const* d_in, const int* in_sizes, int n_in,
                              void* d_out, int out_size) {
    const float* x  = (const float*)d_in[0];
    const float* wm = (const float*)d_in[1];
    float* out = (float*)d_out;

    dim3 grid(HH / TH, CC);   // 16 x 96 = 1536 CTAs
    tvconv_kernel<<<grid, 512>>>(x, wm, out);
}

// round 8
// speedup vs baseline: 1.1519x; 1.1519x over previous
#include <cuda_runtime.h>

// TVConv: per-pixel spatially-varying 3x3 depthwise conv.
// x:           (B=8, C=96, H=128, W=128) f32
// weight_maps: (1, C=96, 3, 3, H=128, W=128) f32
// out:         (B=8, C=96, H=128, W=128) f32
//
// CTA = (channel c, 8-row strip), 256 threads, 4 rows/thread, 36 weight regs
// loaded once and reused across all 8 batches (weight traffic 1x). x tile
// (10x128 interior) staged via 16B cp.async into a TRIPLE buffer: two tile
// loads in flight during every compute phase, and only ONE __syncthreads per
// batch (the buffer staged at iter b was consumed at iter b-1, so the top-of-
// loop barrier protects both the WAR on that buffer and the visibility of the
// freshly waited buffer). Halo columns permanently zero; out-of-range halo
// rows zero-filled via cp.async src-size=0.
//
// (Resubmit of the R4 kernel: prior bench attempt died to a container infra
// failure before measurement.)

#define BB 8
#define CC 96
#define HH 128
#define WW 128
#define TH 8          // output rows per block
#define RPT 4         // rows per thread
#define SPITCH 136    // floats per shared row (4 pad + halo + 128 + halo + pad)
#define TROWS (TH + 2)
#define NBUF 3

__device__ __forceinline__ void cp_async16(void* smem_dst, const void* gsrc, int src_bytes) {
    unsigned saddr = (unsigned)__cvta_generic_to_shared(smem_dst);
    asm volatile("cp.async.cg.shared.global [%0], [%1], 16, %2;\n"
                 :: "r"(saddr), "l"(gsrc), "r"(src_bytes));
}
__device__ __forceinline__ void cp_async_commit() {
    asm volatile("cp.async.commit_group;\n" ::: "memory");
}
template <int N>
__device__ __forceinline__ void cp_async_wait() {
    asm volatile("cp.async.wait_group %0;\n" :: "n"(N) : "memory");
}

__global__ __launch_bounds__(256, 4)
void tvconv_kernel(const float* __restrict__ x,
                   const float* __restrict__ wm,
                   float* __restrict__ out) {
    const int c   = blockIdx.y;
    const int h0  = blockIdx.x * TH;
    const int tid = threadIdx.x;
    const int tw  = tid & (WW - 1);   // 0..127 -> output w
    const int ty  = tid >> 7;         // 0..1

    __shared__ __align__(16) float sx[NBUF][TROWS * SPITCH];

    const int plane = HH * WW;        // 16384
    const float* wmc = wm + c * 9 * plane;

    // ---- halo columns permanently zero (x zero-pad), all 3 buffers ----
    if (tid < NBUF * TROWS * 2) {
        int buf  = tid / (TROWS * 2);
        int rem  = tid - buf * (TROWS * 2);
        int r    = rem >> 1;
        int side = rem & 1;
        sx[buf][r * SPITCH + (side ? 132 : 3)] = 0.0f;
    }

    // ---- load 4x9 weights into registers (coalesced per tap) ----
    float wreg[RPT][9];
    #pragma unroll
    for (int r = 0; r < RPT; r++) {
        const int h = h0 + ty + 2 * r;
        const int base = h * WW + tw;
        #pragma unroll
        for (int t = 0; t < 9; t++) {
            wreg[r][t] = __ldg(&wmc[t * plane + base]);
        }
    }

    const int cplane = c * plane;

    // staging roles: 10 rows x 32 float4 = 320 tasks.
    // tid 0..255 -> rows 0..7; tid 0..63 additionally -> rows 8..9.
    const int sk   = tid & 31;        // float4 index within row
    const int row0 = tid >> 5;        // 0..7
    const int row1 = 8 + (tid >> 5);  // valid only for tid < 64

    auto stage = [&](int b) {
        const float* xb = x + (b * CC) * plane + cplane;
        const int buf = b % NBUF;
        {
            int gh = h0 - 1 + row0;
            int ok = (gh >= 0 && gh < HH);
            cp_async16(&sx[buf][row0 * SPITCH + 4 + 4 * sk],
                       xb + (ok ? gh : 0) * WW + 4 * sk, ok ? 16 : 0);
        }
        if (tid < 64) {
            int gh = h0 - 1 + row1;
            int ok = (gh >= 0 && gh < HH);
            cp_async16(&sx[buf][row1 * SPITCH + 4 + 4 * sk],
                       xb + (ok ? gh : 0) * WW + 4 * sk, ok ? 16 : 0);
        }
        cp_async_commit();
    };

    // preload batches 0 and 1
    stage(0);
    stage(1);

    for (int b = 0; b < BB; b++) {
        if (b < BB - 1) cp_async_wait<1>();   // buf b%3 complete, next still in flight
        else            cp_async_wait<0>();
        __syncthreads();                       // visibility + WAR fence (single barrier/iter)

        if (b + 2 < BB) stage(b + 2);          // targets buffer consumed at iter b-1

        const int p = b % NBUF;
        float* ob = out + (b * CC) * plane + cplane;
        #pragma unroll
        for (int r = 0; r < RPT; r++) {
            const int lr = ty + 2 * r;         // local output row 0..7
            float acc = 0.0f;
            #pragma unroll
            for (int kh = 0; kh < 3; kh++) {
                const float* sr = &sx[p][(lr + kh) * SPITCH + tw + 3];
                acc = fmaf(wreg[r][kh * 3 + 0], sr[0], acc);
                acc = fmaf(wreg[r][kh * 3 + 1], sr[1], acc);
                acc = fmaf(wreg[r][kh * 3 + 2], sr[2], acc);
            }
            ob[(h0 + lr) * WW + tw] = acc;
        }
        // no trailing barrier: next iter's top barrier fences reuse
    }
}

extern "C" void kernel_launch(void* const* d_in, const int* in_sizes, int n_in,
                              void* d_out, int out_size) {
    const float* x  = (const float*)d_in[0];
    const float* wm = (const float*)d_in[1];
    float* out = (float*)d_out;

    dim3 grid(HH / TH, CC);   // 16 x 96 = 1536 CTAs
    tvconv_kernel<<<grid, 256>>>(x, wm, out);
}

// round 9
// speedup vs baseline: 1.1732x; 1.0184x over previous
#include <cuda_runtime.h>

// TVConv: per-pixel spatially-varying 3x3 depthwise conv.
// x:           (B=8, C=96, H=128, W=128) f32
// weight_maps: (1, C=96, 3, 3, H=128, W=128) f32
// out:         (B=8, C=96, H=128, W=128) f32
//
// CTA = (channel c, 8-row strip), 256 threads. Each thread owns a PAIR of
// adjacent w pixels x 2 rows (4 outputs): weights load once as 18x LDG.64
// (float2 per tap), smem reads are scalar+float2+scalar per row (18 LDS/batch
// vs 36), stores are 2x STG.64. Triple-buffered 16B cp.async staging of the
// 10x128 x tile, single __syncthreads per batch (buffer staged at iter b was
// consumed at iter b-1). Halo columns permanently zero; out-of-range halo
// rows zero-filled via cp.async src-size=0.

#define BB 8
#define CC 96
#define HH 128
#define WW 128
#define TH 8          // output rows per block
#define SPITCH 136    // floats per shared row (interior at [4..131], halos [3],[132])
#define TROWS (TH + 2)
#define NBUF 3

__device__ __forceinline__ void cp_async16(void* smem_dst, const void* gsrc, int src_bytes) {
    unsigned saddr = (unsigned)__cvta_generic_to_shared(smem_dst);
    asm volatile("cp.async.cg.shared.global [%0], [%1], 16, %2;\n"
                 :: "r"(saddr), "l"(gsrc), "r"(src_bytes));
}
__device__ __forceinline__ void cp_async_commit() {
    asm volatile("cp.async.commit_group;\n" ::: "memory");
}
template <int N>
__device__ __forceinline__ void cp_async_wait() {
    asm volatile("cp.async.wait_group %0;\n" :: "n"(N) : "memory");
}

__global__ __launch_bounds__(256, 4)
void tvconv_kernel(const float* __restrict__ x,
                   const float* __restrict__ wm,
                   float* __restrict__ out) {
    const int c   = blockIdx.y;
    const int h0  = blockIdx.x * TH;
    const int tid = threadIdx.x;
    const int twx = tid & 63;         // pixel-pair index: w0 = 2*twx
    const int ty  = tid >> 6;         // 0..3 -> row slot

    __shared__ __align__(16) float sx[NBUF][TROWS * SPITCH];

    const int plane = HH * WW;        // 16384
    const float* wmc = wm + c * 9 * plane;

    // ---- halo columns permanently zero (x zero-pad), all 3 buffers ----
    if (tid < NBUF * TROWS * 2) {
        int buf  = tid / (TROWS * 2);
        int rem  = tid - buf * (TROWS * 2);
        int r    = rem >> 1;
        int side = rem & 1;
        sx[buf][r * SPITCH + (side ? 132 : 3)] = 0.0f;
    }

    // ---- load weights: 2 row-groups x 9 taps, float2 per tap (18 LDG.64) ----
    float2 wreg[2][9];
    #pragma unroll
    for (int g = 0; g < 2; g++) {
        const int h = h0 + ty + 4 * g;
        const int base = h * WW + 2 * twx;
        #pragma unroll
        for (int t = 0; t < 9; t++) {
            wreg[g][t] = __ldg((const float2*)&wmc[t * plane + base]);
        }
    }

    const int cplane = c * plane;

    // staging roles: 10 rows x 32 float4 = 320 tasks.
    // tid 0..255 -> rows 0..7; tid 0..63 additionally -> rows 8..9.
    const int sk   = tid & 31;        // float4 index within row
    const int row0 = tid >> 5;        // 0..7
    const int row1 = 8 + (tid >> 5);  // valid only for tid < 64

    auto stage = [&](int b) {
        const float* xb = x + (b * CC) * plane + cplane;
        const int buf = b % NBUF;
        {
            int gh = h0 - 1 + row0;
            int ok = (gh >= 0 && gh < HH);
            cp_async16(&sx[buf][row0 * SPITCH + 4 + 4 * sk],
                       xb + (ok ? gh : 0) * WW + 4 * sk, ok ? 16 : 0);
        }
        if (tid < 64) {
            int gh = h0 - 1 + row1;
            int ok = (gh >= 0 && gh < HH);
            cp_async16(&sx[buf][row1 * SPITCH + 4 + 4 * sk],
                       xb + (ok ? gh : 0) * WW + 4 * sk, ok ? 16 : 0);
        }
        cp_async_commit();
    };

    // preload batches 0 and 1
    stage(0);
    stage(1);

    const int pcol = 4 + 2 * twx;     // smem index of x[w0] (8B aligned)

    for (int b = 0; b < BB; b++) {
        if (b < BB - 1) cp_async_wait<1>();   // buf b%3 complete, next in flight
        else            cp_async_wait<0>();
        __syncthreads();                       // visibility + WAR fence

        if (b + 2 < BB) stage(b + 2);          // targets buffer consumed at b-1

        const int p = b % NBUF;
        float* ob = out + (b * CC) * plane + cplane;
        #pragma unroll
        for (int g = 0; g < 2; g++) {
            const int lr = ty + 4 * g;         // local output row
            float2 acc = make_float2(0.0f, 0.0f);
            #pragma unroll
            for (int kh = 0; kh < 3; kh++) {
                const float* srow = &sx[p][(lr + kh) * SPITCH];
                float  l = srow[pcol - 1];                      // x[w0-1]
                float2 m = *(const float2*)&srow[pcol];         // x[w0], x[w0+1]
                float  r = srow[pcol + 2];                      // x[w0+2]
                const float2 wa = wreg[g][kh * 3 + 0];
                const float2 wb = wreg[g][kh * 3 + 1];
                const float2 wc = wreg[g][kh * 3 + 2];
                acc.x = fmaf(wa.x, l,   acc.x);
                acc.x = fmaf(wb.x, m.x, acc.x);
                acc.x = fmaf(wc.x, m.y, acc.x);
                acc.y = fmaf(wa.y, m.x, acc.y);
                acc.y = fmaf(wb.y, m.y, acc.y);
                acc.y = fmaf(wc.y, r,   acc.y);
            }
            *(float2*)&ob[(h0 + lr) * WW + 2 * twx] = acc;
        }
        // no trailing barrier: next iter's top barrier fences reuse
    }
}

extern "C" void kernel_launch(void* const* d_in, const int* in_sizes, int n_in,
                              void* d_out, int out_size) {
    const float* x  = (const float*)d_in[0];
    const float* wm = (const float*)d_in[1];
    float* out = (float*)d_out;

    dim3 grid(HH / TH, CC);   // 16 x 96 = 1536 CTAs
    tvconv_kernel<<<grid, 256>>>(x, wm, out);
}

// round 10
// speedup vs baseline: 1.1768x; 1.0031x over previous
#include <cuda_runtime.h>

// TVConv: per-pixel spatially-varying 3x3 depthwise conv.
// x:           (B=8, C=96, H=128, W=128) f32
// weight_maps: (1, C=96, 3, 3, H=128, W=128) f32
// out:         (B=8, C=96, H=128, W=128) f32
//
// CTA = (channel c, 8-row strip), 256 threads, scalar per-pixel compute
// (conflict-free LDS). ALL 8 batch x-tiles get their own smem buffer
// (8 x 10 x 136 floats = 43.5 KB, still 4 CTAs/SM): the prologue issues all
// 8 cp.async tile groups, then the 36 weight LDGs (their latency overlaps
// tile arrival). Compute proceeds in 4 phases of 2 batches gated by
// cp.async.wait_group<6/4/2/0> + one __syncthreads each -> only 4 barriers
// per CTA, zero WAR hazards (no buffer reuse), ~8 tiles of DRAM MLP on the
// ramp. Halo columns permanently zero; out-of-range halo rows zero-filled
// via cp.async src-size=0.

#define BB 8
#define CC 96
#define HH 128
#define WW 128
#define TH 8          // output rows per block
#define RPT 4         // rows per thread
#define SPITCH 136    // floats per shared row (interior [4..131], halos [3],[132])
#define TROWS (TH + 2)

__device__ __forceinline__ void cp_async16(void* smem_dst, const void* gsrc, int src_bytes) {
    unsigned saddr = (unsigned)__cvta_generic_to_shared(smem_dst);
    asm volatile("cp.async.cg.shared.global [%0], [%1], 16, %2;\n"
                 :: "r"(saddr), "l"(gsrc), "r"(src_bytes));
}
__device__ __forceinline__ void cp_async_commit() {
    asm volatile("cp.async.commit_group;\n" ::: "memory");
}
template <int N>
__device__ __forceinline__ void cp_async_wait() {
    asm volatile("cp.async.wait_group %0;\n" :: "n"(N) : "memory");
}

__global__ __launch_bounds__(256, 4)
void tvconv_kernel(const float* __restrict__ x,
                   const float* __restrict__ wm,
                   float* __restrict__ out) {
    const int c   = blockIdx.y;
    const int h0  = blockIdx.x * TH;
    const int tid = threadIdx.x;
    const int tw  = tid & (WW - 1);   // 0..127 -> output w
    const int ty  = tid >> 7;         // 0..1

    __shared__ __align__(16) float sx[BB][TROWS * SPITCH];   // 43,520 B

    const int plane  = HH * WW;       // 16384
    const int cplane = c * plane;
    const float* wmc = wm + c * 9 * plane;

    // ---- halo columns permanently zero (x zero-pad), all 8 buffers ----
    // 8 bufs x 10 rows x 2 cols = 160 writes, one per thread.
    if (tid < BB * TROWS * 2) {
        int buf  = tid / (TROWS * 2);
        int rem  = tid - buf * (TROWS * 2);
        int r    = rem >> 1;
        int side = rem & 1;
        sx[buf][r * SPITCH + (side ? 132 : 3)] = 0.0f;
    }

    // staging roles: 10 rows x 32 float4 = 320 tasks per tile.
    // tid 0..255 -> rows 0..7; tid 0..63 additionally -> rows 8..9.
    const int sk   = tid & 31;        // float4 index within row
    const int row0 = tid >> 5;        // 0..7
    const int row1 = 8 + (tid >> 5);  // valid only for tid < 64

    const int gh0 = h0 - 1 + row0;
    const int ok0 = (gh0 >= 0 && gh0 < HH);
    const int off0 = (ok0 ? gh0 : 0) * WW + 4 * sk;
    const int gh1 = h0 - 1 + row1;
    const int ok1 = (gh1 >= 0 && gh1 < HH);
    const int off1 = (ok1 ? gh1 : 0) * WW + 4 * sk;

    // ---- issue ALL 8 tile loads (one commit group per batch) ----
    #pragma unroll
    for (int b = 0; b < BB; b++) {
        const float* xb = x + (b * CC) * plane + cplane;
        cp_async16(&sx[b][row0 * SPITCH + 4 + 4 * sk], xb + off0, ok0 ? 16 : 0);
        if (tid < 64)
            cp_async16(&sx[b][row1 * SPITCH + 4 + 4 * sk], xb + off1, ok1 ? 16 : 0);
        cp_async_commit();
    }

    // ---- load 4x9 weights into registers (latency overlaps tile arrival) ----
    float wreg[RPT][9];
    #pragma unroll
    for (int r = 0; r < RPT; r++) {
        const int h = h0 + ty + 2 * r;
        const int base = h * WW + tw;
        #pragma unroll
        for (int t = 0; t < 9; t++) {
            wreg[r][t] = __ldg(&wmc[t * plane + base]);
        }
    }

    // ---- consume in 4 phases of 2 batches ----
    #define COMPUTE_BATCH(B)                                                  \
    {                                                                         \
        float* ob = out + ((B) * CC) * plane + cplane;                        \
        _Pragma("unroll")                                                     \
        for (int r = 0; r < RPT; r++) {                                       \
            const int lr = ty + 2 * r;                                        \
            float acc = 0.0f;                                                 \
            _Pragma("unroll")                                                 \
            for (int kh = 0; kh < 3; kh++) {                                  \
                const float* sr = &sx[(B)][(lr + kh) * SPITCH + tw + 3];      \
                acc = fmaf(wreg[r][kh * 3 + 0], sr[0], acc);                  \
                acc = fmaf(wreg[r][kh * 3 + 1], sr[1], acc);                  \
                acc = fmaf(wreg[r][kh * 3 + 2], sr[2], acc);                  \
            }                                                                 \
            ob[(h0 + lr) * WW + tw] = acc;                                    \
        }                                                                     \
    }

    cp_async_wait<6>(); __syncthreads();
    COMPUTE_BATCH(0) COMPUTE_BATCH(1)
    cp_async_wait<4>(); __syncthreads();
    COMPUTE_BATCH(2) COMPUTE_BATCH(3)
    cp_async_wait<2>(); __syncthreads();
    COMPUTE_BATCH(4) COMPUTE_BATCH(5)
    cp_async_wait<0>(); __syncthreads();
    COMPUTE_BATCH(6) COMPUTE_BATCH(7)

    #undef COMPUTE_BATCH
}

extern "C" void kernel_launch(void* const* d_in, const int* in_sizes, int n_in,
                              void* d_out, int out_size) {
    const float* x  = (const float*)d_in[0];
    const float* wm = (const float*)d_in[1];
    float* out = (float*)d_out;

    dim3 grid(HH / TH, CC);   // 16 x 96 = 1536 CTAs
    tvconv_kernel<<<grid, 256>>>(x, wm, out);
}